// round 17
// baseline (speedup 1.0000x reference)
#include <cuda_runtime.h>
#include <cstdint>

// Shapes (fixed by setup_inputs):
//   k_cache: (B=4, H=8, D=128, 128, 64) f32 -> (BH=32, D=128, SFULL=8192)
//   v_cache: (B=4, H=8, 128, 64, D=128) f32 -> (BH=32, SFULL=8192, D=128)
//   S = 6144 (derived from out_size)
// out = stack([transpose_k(:, :, :S), v(:, :S, :)]) -> (2, BH, S, D)
//
// FINAL kernel — session best (63.68 us total, kernel 56.03 us @ 6.23 TB/s,
// 78.6% dram__cycles_active = the mixed 2R+2W HBM3e ceiling on GB300):
//   - interleaved independent 16 KB blocks (even = K-transpose, odd = V-copy)
//   - native 256-bit (v4.b64) global accesses on all contiguous streams
//   - conflict-free [32][129] tile; scalar drain = contiguous 128 B per warp,
//     fully contiguous 16 KB output region per block
//   - 8 CTAs/SM, 32 regs, 17 KB smem
// All alternative levers (tiles, persistence, hints, waves, CE, widths)
// measured neutral or worse across rounds 2-16.

#define BH_    32
#define D_     128
#define SFULL_ 8192

struct f8 { uint64_t a, b, c, d; };   // 32-byte chunk = 8 floats

__device__ __forceinline__ f8 ldg256(const void* p) {
    f8 v;
    asm("ld.global.v4.b64 {%0,%1,%2,%3}, [%4];"
        : "=l"(v.a), "=l"(v.b), "=l"(v.c), "=l"(v.d)
        : "l"(p));
    return v;
}

__device__ __forceinline__ void stg256(void* p, f8 v) {
    asm volatile("st.global.v4.b64 [%0], {%1,%2,%3,%4};"
                 :: "l"(p), "l"(v.a), "l"(v.b), "l"(v.c), "l"(v.d)
                 : "memory");
}

__device__ __forceinline__ void unpack2(uint64_t w, float& lo, float& hi) {
    lo = __uint_as_float((uint32_t)w);
    hi = __uint_as_float((uint32_t)(w >> 32));
}

__global__ __launch_bounds__(256) void fused_kv_kernel(
    const float* __restrict__ kin,
    const float* __restrict__ vin,
    float*       __restrict__ outk,
    float*       __restrict__ outv,
    int S, int tilesPerBh)
{
    const int b  = blockIdx.x;
    const int t  = threadIdx.x;
    const int id = b >> 1;
    const int bh = id / tilesPerBh;
    const int jj = id - bh * tilesPerBh;

    if (b & 1) {
        // ---------- V copy: contiguous 16 KB chunk, 256-bit accesses --------
        const float* src = vin  + (size_t)bh * (SFULL_ * D_) + (size_t)jj * 4096;
        float*       dst = outv + (size_t)bh * ((size_t)S * D_) + (size_t)jj * 4096;

        f8 v0 = ldg256(src + 8 * (size_t)t);
        f8 v1 = ldg256(src + 8 * (size_t)(t + 256));
        stg256(dst + 8 * (size_t)t,         v0);
        stg256(dst + 8 * (size_t)(t + 256), v1);
    } else {
        // --------------- K transpose: (D=128, s=32) -> (s=32, D=128) --------
        // tile[s][d], row stride 129 floats:
        //   STS (8 consecutive s at fixed d): conflict-free
        //   LDS bank = (s+d)%32: conflict-free
        __shared__ float tile[32][129];

        const int s0 = jj * 32;
        const float* src = kin  + (size_t)bh * D_ * SFULL_ + s0;
        float*       dst = outk + (size_t)bh * (size_t)S * D_ + (size_t)s0 * D_;

        // Load: 512 x 32 B chunks; chunk idx -> (d = idx>>2, g = idx&3),
        // covering s = 8g..8g+7 of row d. Each 4-lane group reads a
        // contiguous 128 B of one d-row.
        f8 r[2];
#pragma unroll
        for (int i = 0; i < 2; ++i) {
            const int idx = t + i * 256;      // 0..511
            const int d = idx >> 2;           // 0..127
            const int g = idx & 3;            // 0..3
            r[i] = ldg256(src + (size_t)d * SFULL_ + 8 * g);
        }
#pragma unroll
        for (int i = 0; i < 2; ++i) {
            const int idx = t + i * 256;
            const int d = idx >> 2;
            const int g = idx & 3;
            float e0, e1, e2, e3, e4, e5, e6, e7;
            unpack2(r[i].a, e0, e1);
            unpack2(r[i].b, e2, e3);
            unpack2(r[i].c, e4, e5);
            unpack2(r[i].d, e6, e7);
            const int sb = 8 * g;
            tile[sb + 0][d] = e0;
            tile[sb + 1][d] = e1;
            tile[sb + 2][d] = e2;
            tile[sb + 3][d] = e3;
            tile[sb + 4][d] = e4;
            tile[sb + 5][d] = e5;
            tile[sb + 6][d] = e6;
            tile[sb + 7][d] = e7;
        }
        __syncthreads();

        // Drain: scalar, each warp writes a contiguous 128 B segment; block
        // writes a fully contiguous 16 KB output region.
#pragma unroll
        for (int i = 0; i < 16; ++i) {
            const int e = t + i * 256;
            const int s = e >> 7;             // 0..31
            const int d = e & 127;            // 0..127
            dst[(size_t)s * D_ + d] = tile[s][d];
        }
    }
}

extern "C" void kernel_launch(void* const* d_in, const int* in_sizes, int n_in,
                              void* d_out, int out_size) {
    const float* k_cache = (const float*)d_in[0];
    const float* v_cache = (const float*)d_in[1];
    // seq_len is fully determined by out_size: out = 2 * BH * S * D elems.
    const int S = out_size / (2 * BH_ * D_);        // 6144
    const int tilesPerBh = S / 32;                  // 192

    float* out_k = (float*)d_out;                                   // (BH,S,D)
    float* out_v = (float*)d_out + (size_t)BH_ * S * D_;

    dim3 block(256, 1, 1);
    dim3 grid((unsigned)(2 * BH_ * tilesPerBh), 1, 1);              // 12288
    fused_kv_kernel<<<grid, block>>>(k_cache, v_cache, out_k, out_v,
                                     S, tilesPerBh);
}